// round 8
// baseline (speedup 1.0000x reference)
#include <cuda_runtime.h>
#include <cuda_bf16.h>
#include <cstddef>

// Problem constants
#define BB   1024          // batch (both i and j extents)
#define TT   12            // time steps
#define DD   512           // feature dim
#define ROWSTRIDE (TT*DD)  // stride between consecutive batch rows in [B,T,D]

// Scratch: dots[t][i][j] fp32, plus per-column results.
__device__ float g_dots[(size_t)TT * BB * BB];           // 50.3 MB
__device__ float g_col[2 * TT * BB];                     // [0:12288) diag-lse, [12288:24576) correct

// ---------------------------------------------------------------------------
// Phase A: 12 batched SGEMMs  C_t[i][j] = sum_d X[i,t,d] * P[j,t,d]
// Tile: 128x128 per block, K-tile 8, 256 threads, 8x8 per thread,
// double-buffered shared memory, float4 global loads.
// ---------------------------------------------------------------------------
__global__ __launch_bounds__(256, 2)
void cpc_gemm_kernel(const float* __restrict__ X,   // x_future_encoded [B,T,D] (rows i)
                     const float* __restrict__ P)   // predictions      [B,T,D] (rows j)
{
    const int t  = blockIdx.z;
    const int ib = blockIdx.y * 128;
    const int jb = blockIdx.x * 128;

    __shared__ float As[2][8][128];
    __shared__ float Bs[2][8][128];

    const int tid = threadIdx.x;
    const int tx  = tid & 15;        // column micro-tile selector
    const int ty  = tid >> 4;        // row micro-tile selector

    // Global-load mapping: each thread loads one float4 from A and one from B per k-tile.
    const int lrow = tid >> 1;            // 0..127
    const int lc4  = (tid & 1) * 4;       // 0 or 4 (k offset within 8-wide tile)

    const float* Aptr = X + ((size_t)(ib + lrow) * TT + t) * DD + lc4;
    const float* Bptr = P + ((size_t)(jb + lrow) * TT + t) * DD + lc4;

    float acc[8][8];
    #pragma unroll
    for (int a = 0; a < 8; a++)
        #pragma unroll
        for (int b = 0; b < 8; b++) acc[a][b] = 0.f;

    // Preload k-tile 0
    float4 av = *reinterpret_cast<const float4*>(Aptr);
    float4 bv = *reinterpret_cast<const float4*>(Bptr);
    As[0][lc4 + 0][lrow] = av.x; As[0][lc4 + 1][lrow] = av.y;
    As[0][lc4 + 2][lrow] = av.z; As[0][lc4 + 3][lrow] = av.w;
    Bs[0][lc4 + 0][lrow] = bv.x; Bs[0][lc4 + 1][lrow] = bv.y;
    Bs[0][lc4 + 2][lrow] = bv.z; Bs[0][lc4 + 3][lrow] = bv.w;
    __syncthreads();

    int buf = 0;
    const int NKT = DD / 8;   // 64 k-tiles
    for (int kt = 0; kt < NKT; kt++) {
        if (kt < NKT - 1) {
            av = *reinterpret_cast<const float4*>(Aptr + (kt + 1) * 8);
            bv = *reinterpret_cast<const float4*>(Bptr + (kt + 1) * 8);
        }
        #pragma unroll
        for (int k = 0; k < 8; k++) {
            float ar[8], br[8];
            *reinterpret_cast<float4*>(ar)     = *reinterpret_cast<const float4*>(&As[buf][k][ty * 4]);
            *reinterpret_cast<float4*>(ar + 4) = *reinterpret_cast<const float4*>(&As[buf][k][ty * 4 + 64]);
            *reinterpret_cast<float4*>(br)     = *reinterpret_cast<const float4*>(&Bs[buf][k][tx * 4]);
            *reinterpret_cast<float4*>(br + 4) = *reinterpret_cast<const float4*>(&Bs[buf][k][tx * 4 + 64]);
            #pragma unroll
            for (int ii = 0; ii < 8; ii++)
                #pragma unroll
                for (int jj = 0; jj < 8; jj++)
                    acc[ii][jj] += ar[ii] * br[jj];
        }
        if (kt < NKT - 1) {
            buf ^= 1;
            As[buf][lc4 + 0][lrow] = av.x; As[buf][lc4 + 1][lrow] = av.y;
            As[buf][lc4 + 2][lrow] = av.z; As[buf][lc4 + 3][lrow] = av.w;
            Bs[buf][lc4 + 0][lrow] = bv.x; Bs[buf][lc4 + 1][lrow] = bv.y;
            Bs[buf][lc4 + 2][lrow] = bv.z; Bs[buf][lc4 + 3][lrow] = bv.w;
            __syncthreads();
        }
    }

    // Epilogue: write C tile
    float* Cbase = g_dots + (size_t)t * BB * BB;
    #pragma unroll
    for (int ii = 0; ii < 8; ii++) {
        int row = ib + ty * 4 + ((ii < 4) ? ii : (64 + ii - 4));
        float4 v0 = make_float4(acc[ii][0], acc[ii][1], acc[ii][2], acc[ii][3]);
        float4 v1 = make_float4(acc[ii][4], acc[ii][5], acc[ii][6], acc[ii][7]);
        *reinterpret_cast<float4*>(&Cbase[(size_t)row * BB + jb + tx * 4])      = v0;
        *reinterpret_cast<float4*>(&Cbase[(size_t)row * BB + jb + tx * 4 + 64]) = v1;
    }
}

// ---------------------------------------------------------------------------
// Phase B: per-column (t,j) online max/argmax + thresholded exp-sum + diag.
// Warp threads map consecutive j -> fully coalesced 128B row reads.
// exp() only fires for v - m > -30 (negligible tail) or a new running max
// (~7.5x per column): ~130K MUFU ops total instead of 12.6M.
// ---------------------------------------------------------------------------
__device__ __forceinline__ void col_step(float v, int idx, int j,
                                         float& m, float& s, int& am, float& diag)
{
    if (idx == j) diag = v;
    if (v > m) {
        s = s * __expf(m - v) + 1.0f;   // expf(-inf)=0 handles the first element
        m = v; am = idx;
    } else {
        float d = v - m;
        if (d > -30.0f) s += __expf(d);
    }
}

__global__ __launch_bounds__(256)
void cpc_colreduce_kernel()
{
    const int gid = blockIdx.x * blockDim.x + threadIdx.x;   // 0..12287
    const int t = gid >> 10;
    const int j = gid & (BB - 1);
    const float* __restrict__ col = g_dots + (size_t)t * BB * BB + j;

    float m = -3.402823466e38f;
    float s = 0.0f;
    float diag = 0.0f;
    int   am = 0;

    for (int i = 0; i < BB; i += 4) {
        float v0 = col[(size_t)(i + 0) * BB];
        float v1 = col[(size_t)(i + 1) * BB];
        float v2 = col[(size_t)(i + 2) * BB];
        float v3 = col[(size_t)(i + 3) * BB];
        col_step(v0, i + 0, j, m, s, am, diag);
        col_step(v1, i + 1, j, m, s, am, diag);
        col_step(v2, i + 2, j, m, s, am, diag);
        col_step(v3, i + 3, j, m, s, am, diag);
    }

    const float lse = m + __logf(s);
    g_col[gid]             = diag - lse;                 // log_softmax diagonal
    g_col[gid + TT * BB]   = (am == j) ? 1.0f : 0.0f;    // argmax correctness
}

// ---------------------------------------------------------------------------
// Phase C: deterministic single-block tree reduction -> (-loss, accuracy)
// ---------------------------------------------------------------------------
__global__ __launch_bounds__(1024)
void cpc_finalize_kernel(float* __restrict__ out)
{
    __shared__ float sv[1024];
    __shared__ float sc[1024];
    const int tid = threadIdx.x;
    const int N = TT * BB;   // 12288

    float v = 0.f, c = 0.f;
    for (int k = tid; k < N; k += 1024) {
        v += g_col[k];
        c += g_col[k + N];
    }
    sv[tid] = v; sc[tid] = c;
    __syncthreads();
    #pragma unroll
    for (int st = 512; st > 0; st >>= 1) {
        if (tid < st) { sv[tid] += sv[tid + st]; sc[tid] += sc[tid + st]; }
        __syncthreads();
    }
    if (tid == 0) {
        // loss = mean_b( sum_t diag_ls / T ) = sum_all / (T*B); return -loss
        out[0] = -(sv[0] / (float)N);
        out[1] = sc[0] / (float)N;
    }
}

// ---------------------------------------------------------------------------
extern "C" void kernel_launch(void* const* d_in, const int* in_sizes, int n_in,
                              void* d_out, int out_size)
{
    const float* predictions = (const float*)d_in[0];   // rows j
    const float* x_future    = (const float*)d_in[1];   // rows i
    float* out = (float*)d_out;

    dim3 ggrid(BB / 128, BB / 128, TT);   // (8, 8, 12)
    cpc_gemm_kernel<<<ggrid, 256>>>(x_future, predictions);

    cpc_colreduce_kernel<<<(TT * BB) / 256, 256>>>();   // 48 blocks

    cpc_finalize_kernel<<<1, 1024>>>(out);
}

// round 9
// speedup vs baseline: 1.3146x; 1.3146x over previous
#include <cuda_runtime.h>
#include <cuda_bf16.h>
#include <cstddef>

#define BB   1024
#define TT   12
#define DD   512

typedef unsigned long long u64;

// Per-chunk partials: [t][chunk(8)][j]
__device__ float g_pm  [TT * 8 * BB];
__device__ float g_ps  [TT * 8 * BB];
__device__ int   g_pam [TT * 8 * BB];
__device__ float g_diag[TT * BB];
__device__ float g_col [2 * TT * BB];

#define FFMA2(c, a, b) asm("fma.rn.f32x2 %0, %1, %2, %0;" : "+l"(c) : "l"(a), "l"(b))
#define UNPK(lo, hi, p) asm("mov.b64 {%0,%1}, %2;" : "=f"(lo), "=f"(hi) : "l"(p))

// ---------------------------------------------------------------------------
// Fused GEMM + per-chunk column softmax-stats.
// C_t[i][j] = sum_d X[i,t,d]*P[j,t,d]; 128x128 tile, K-tile 8, 256 thr,
// 8x8 per thread via packed f32x2 FMA (A duplicated in smem -> ready pairs).
// Epilogue: per-column (over 128 rows) max/argmax/sum-exp/diag -> g_p*.
// ---------------------------------------------------------------------------
__global__ __launch_bounds__(256, 2)
void cpc_gemm_fused_kernel(const float* __restrict__ X,   // x_future [B,T,D] (rows i)
                           const float* __restrict__ P)   // predictions    (rows j)
{
    const int t  = blockIdx.z;
    const int ic = blockIdx.y;          // row chunk 0..7
    const int ib = ic * 128;
    const int jb = blockIdx.x * 128;

    __shared__ __align__(16) union {
        struct { float A[2][8][256]; float B[2][8][128]; } gm;   // 24 KB
        struct {
            float m[16][128]; int idx[16][128];
            float s[16][128];
            float m128[128];  int am128[128];
        } red;                                                    // 25.5 KB
    } sm;

    const int tid = threadIdx.x;
    const int tx  = tid & 15;
    const int ty  = tid >> 4;

    const int lrow = tid >> 1;
    const int lc4  = (tid & 1) * 4;

    const float* Aptr = X + ((size_t)(ib + lrow) * TT + t) * DD + lc4;
    const float* Bptr = P + ((size_t)(jb + lrow) * TT + t) * DD + lc4;

    u64 acc2[8][4];
    #pragma unroll
    for (int a = 0; a < 8; a++)
        #pragma unroll
        for (int b = 0; b < 4; b++) acc2[a][b] = 0ull;

    // Preload k-tile 0 (A stored duplicated: float 2r,2r+1 = row r)
    float4 av = *reinterpret_cast<const float4*>(Aptr);
    float4 bv = *reinterpret_cast<const float4*>(Bptr);
    {
        float2* Ad = reinterpret_cast<float2*>(&sm.gm.A[0][0][0]);
        #pragma unroll
        for (int q = 0; q < 4; q++) {
            float v = (q == 0) ? av.x : (q == 1) ? av.y : (q == 2) ? av.z : av.w;
            Ad[(lc4 + q) * 128 + lrow] = make_float2(v, v);
        }
        sm.gm.B[0][lc4 + 0][lrow] = bv.x; sm.gm.B[0][lc4 + 1][lrow] = bv.y;
        sm.gm.B[0][lc4 + 2][lrow] = bv.z; sm.gm.B[0][lc4 + 3][lrow] = bv.w;
    }
    __syncthreads();

    int buf = 0;
    const int NKT = DD / 8;
    for (int kt = 0; kt < NKT; kt++) {
        if (kt < NKT - 1) {
            av = *reinterpret_cast<const float4*>(Aptr + (kt + 1) * 8);
            bv = *reinterpret_cast<const float4*>(Bptr + (kt + 1) * 8);
        }
        #pragma unroll
        for (int k = 0; k < 8; k++) {
            // A pairs (value duplicated): rows ty*4..+3 and 64+ty*4..+3
            ulonglong2 a01 = *reinterpret_cast<const ulonglong2*>(&sm.gm.A[buf][k][ty * 8]);
            ulonglong2 a23 = *reinterpret_cast<const ulonglong2*>(&sm.gm.A[buf][k][ty * 8 + 4]);
            ulonglong2 a45 = *reinterpret_cast<const ulonglong2*>(&sm.gm.A[buf][k][128 + ty * 8]);
            ulonglong2 a67 = *reinterpret_cast<const ulonglong2*>(&sm.gm.A[buf][k][128 + ty * 8 + 4]);
            // B col-pairs
            ulonglong2 b01 = *reinterpret_cast<const ulonglong2*>(&sm.gm.B[buf][k][tx * 4]);
            ulonglong2 b23 = *reinterpret_cast<const ulonglong2*>(&sm.gm.B[buf][k][tx * 4 + 64]);

            u64 a2[8] = { a01.x, a01.y, a23.x, a23.y, a45.x, a45.y, a67.x, a67.y };
            u64 b2[4] = { b01.x, b01.y, b23.x, b23.y };
            #pragma unroll
            for (int ii = 0; ii < 8; ii++) {
                FFMA2(acc2[ii][0], a2[ii], b2[0]);
                FFMA2(acc2[ii][1], a2[ii], b2[1]);
                FFMA2(acc2[ii][2], a2[ii], b2[2]);
                FFMA2(acc2[ii][3], a2[ii], b2[3]);
            }
        }
        if (kt < NKT - 1) {
            buf ^= 1;
            __syncthreads();
            float2* Ad = reinterpret_cast<float2*>(&sm.gm.A[buf][0][0]);
            #pragma unroll
            for (int q = 0; q < 4; q++) {
                float v = (q == 0) ? av.x : (q == 1) ? av.y : (q == 2) ? av.z : av.w;
                Ad[(lc4 + q) * 128 + lrow] = make_float2(v, v);
            }
            sm.gm.B[buf][lc4 + 0][lrow] = bv.x; sm.gm.B[buf][lc4 + 1][lrow] = bv.y;
            sm.gm.B[buf][lc4 + 2][lrow] = bv.z; sm.gm.B[buf][lc4 + 3][lrow] = bv.w;
            __syncthreads();
        }
    }

    // Unpack accumulators: accf[ii][jj]; col jj<4 -> tx*4+jj, else 64+tx*4+jj-4
    float accf[8][8];
    #pragma unroll
    for (int ii = 0; ii < 8; ii++)
        #pragma unroll
        for (int jp = 0; jp < 4; jp++)
            UNPK(accf[ii][2 * jp], accf[ii][2 * jp + 1], acc2[ii][jp]);

    // Diagonal: only blocks with ib==jb contain (i==j) elements; thread owns
    // them iff tx==ty at (ii==jj) positions in each half.
    if (ib == jb && tx == ty) {
        #pragma unroll
        for (int q = 0; q < 4; q++) {
            g_diag[t * BB + jb + tx * 4 + q]      = accf[q][q];
            g_diag[t * BB + jb + 64 + tx * 4 + q] = accf[4 + q][4 + q];
        }
    }

    __syncthreads();   // done with gm smem

    // Step 1: per-thread column max/argmax over its 8 rows
    #pragma unroll
    for (int jj = 0; jj < 8; jj++) {
        const int c = (jj < 4) ? tx * 4 + jj : 64 + tx * 4 + (jj - 4);
        float m = -3.402823466e38f; int arow = 0;
        #pragma unroll
        for (int ii = 0; ii < 8; ii++) {
            float v = accf[ii][jj];
            int grow = ib + ((ii < 4) ? ty * 4 + ii : 64 + ty * 4 + (ii - 4));
            if (v > m) { m = v; arow = grow; }
        }
        sm.red.m[ty][c] = m;
        sm.red.idx[ty][c] = arow;
    }
    __syncthreads();

    // Step 2: reduce 16 -> block-column max/argmax
    if (tid < 128) {
        float m = -3.402823466e38f; int am = 0;
        #pragma unroll
        for (int k = 0; k < 16; k++) {
            float v = sm.red.m[k][tid];
            if (v > m) { m = v; am = sm.red.idx[k][tid]; }
        }
        sm.red.m128[tid] = m;
        sm.red.am128[tid] = am;
    }
    __syncthreads();

    // Step 3: thresholded sum-exp vs block max (cuts ~90% of expf)
    #pragma unroll
    for (int jj = 0; jj < 8; jj++) {
        const int c = (jj < 4) ? tx * 4 + jj : 64 + tx * 4 + (jj - 4);
        const float M = sm.red.m128[c];
        float s = 0.f;
        #pragma unroll
        for (int ii = 0; ii < 8; ii++) {
            float d = accf[ii][jj] - M;
            if (d > -30.0f) s += __expf(d);
        }
        sm.red.s[ty][c] = s;
    }
    __syncthreads();

    // Step 4: reduce s, write partials
    if (tid < 128) {
        float s = 0.f;
        #pragma unroll
        for (int k = 0; k < 16; k++) s += sm.red.s[k][tid];
        const int pidx = ((t * 8 + ic) * BB) + jb + tid;
        g_pm[pidx]  = sm.red.m128[tid];
        g_ps[pidx]  = s;
        g_pam[pidx] = sm.red.am128[tid];
    }
}

// ---------------------------------------------------------------------------
// Combine 8 chunk-partials per column -> log_softmax diag + correctness flag
// ---------------------------------------------------------------------------
__global__ __launch_bounds__(256)
void cpc_combine_kernel()
{
    const int gid = blockIdx.x * blockDim.x + threadIdx.x;   // 0..12287
    const int t = gid >> 10;
    const int j = gid & (BB - 1);
    const int base = t * 8 * BB + j;

    float m = -3.402823466e38f; int am = 0;
    #pragma unroll
    for (int k = 0; k < 8; k++) {
        float mk = g_pm[base + k * BB];
        if (mk > m) { m = mk; am = g_pam[base + k * BB]; }
    }
    float s = 0.f;
    #pragma unroll
    for (int k = 0; k < 8; k++)
        s += g_ps[base + k * BB] * __expf(g_pm[base + k * BB] - m);

    const float lse = m + __logf(s);
    g_col[gid]           = g_diag[gid] - lse;
    g_col[gid + TT * BB] = (am == j) ? 1.0f : 0.0f;
}

// ---------------------------------------------------------------------------
// Deterministic single-block reduction -> (-loss, accuracy)
// ---------------------------------------------------------------------------
__global__ __launch_bounds__(1024)
void cpc_finalize_kernel(float* __restrict__ out)
{
    __shared__ float sv[1024];
    __shared__ float sc[1024];
    const int tid = threadIdx.x;
    const int N = TT * BB;

    float v = 0.f, c = 0.f;
    for (int k = tid; k < N; k += 1024) {
        v += g_col[k];
        c += g_col[k + N];
    }
    sv[tid] = v; sc[tid] = c;
    __syncthreads();
    #pragma unroll
    for (int st = 512; st > 0; st >>= 1) {
        if (tid < st) { sv[tid] += sv[tid + st]; sc[tid] += sc[tid + st]; }
        __syncthreads();
    }
    if (tid == 0) {
        out[0] = -(sv[0] / (float)N);
        out[1] = sc[0] / (float)N;
    }
}

// ---------------------------------------------------------------------------
extern "C" void kernel_launch(void* const* d_in, const int* in_sizes, int n_in,
                              void* d_out, int out_size)
{
    const float* predictions = (const float*)d_in[0];
    const float* x_future    = (const float*)d_in[1];
    float* out = (float*)d_out;

    dim3 ggrid(BB / 128, BB / 128, TT);   // (8, 8, 12)
    cpc_gemm_fused_kernel<<<ggrid, 256>>>(x_future, predictions);
    cpc_combine_kernel<<<(TT * BB) / 256, 256>>>();
    cpc_finalize_kernel<<<1, 1024>>>(out);
}

// round 10
// speedup vs baseline: 1.4151x; 1.0764x over previous
#include <cuda_runtime.h>
#include <cuda_bf16.h>
#include <cstddef>

#define BB   1024
#define TT   12
#define DD   512

typedef unsigned long long u64;

// Per-chunk partials: [t][chunk(8)][j]
__device__ float g_pm  [TT * 8 * BB];
__device__ float g_ps  [TT * 8 * BB];
__device__ int   g_pam [TT * 8 * BB];
__device__ float g_diag[TT * BB];
__device__ float g_col [2 * TT * BB];

#define FFMA2(c, a, b) asm("fma.rn.f32x2 %0, %1, %2, %0;" : "+l"(c) : "l"(a), "l"(b))
#define UNPK(lo, hi, p) asm("mov.b64 {%0,%1}, %2;" : "=f"(lo), "=f"(hi) : "l"(p))

// ---------------------------------------------------------------------------
// Fused GEMM + per-chunk column softmax-stats.
// 128x128 tile, K-tile 8, 256 thr, 8x8 per thread via packed fma.rn.f32x2
// (A stored duplicated in smem so LDS.128 yields ready (a,a) pairs).
// Double-buffered with a SINGLE barrier per k-tile (store to buf^1, sync).
// Epilogue: per-column (128-row chunk) max/argmax/sum-exp/diag partials.
// ---------------------------------------------------------------------------
__global__ __launch_bounds__(256, 2)
void cpc_gemm_fused_kernel(const float* __restrict__ X,   // x_future [B,T,D] (rows i)
                           const float* __restrict__ P)   // predictions    (rows j)
{
    const int t  = blockIdx.z;
    const int ic = blockIdx.y;          // row chunk 0..7
    const int ib = ic * 128;
    const int jb = blockIdx.x * 128;

    __shared__ __align__(16) union {
        struct { float A[2][8][256]; float B[2][8][128]; } gm;   // 24 KB
        struct {
            float m[16][128]; int idx[16][128];
            float s[16][128];
            float m128[128];  int am128[128];
        } red;                                                    // 25.5 KB
    } sm;

    const int tid = threadIdx.x;
    const int tx  = tid & 15;
    const int ty  = tid >> 4;

    const int lrow = tid >> 1;
    const int lc4  = (tid & 1) * 4;

    const float* Aptr = X + ((size_t)(ib + lrow) * TT + t) * DD + lc4;
    const float* Bptr = P + ((size_t)(jb + lrow) * TT + t) * DD + lc4;

    u64 acc2[8][4];
    #pragma unroll
    for (int a = 0; a < 8; a++)
        #pragma unroll
        for (int b = 0; b < 4; b++) acc2[a][b] = 0ull;

    // Preload k-tile 0 (A duplicated: float2 slot r holds (row_r, row_r))
    float4 av = *reinterpret_cast<const float4*>(Aptr);
    float4 bv = *reinterpret_cast<const float4*>(Bptr);
    {
        float2* Ad = reinterpret_cast<float2*>(&sm.gm.A[0][0][0]);
        Ad[(lc4 + 0) * 128 + lrow] = make_float2(av.x, av.x);
        Ad[(lc4 + 1) * 128 + lrow] = make_float2(av.y, av.y);
        Ad[(lc4 + 2) * 128 + lrow] = make_float2(av.z, av.z);
        Ad[(lc4 + 3) * 128 + lrow] = make_float2(av.w, av.w);
        sm.gm.B[0][lc4 + 0][lrow] = bv.x; sm.gm.B[0][lc4 + 1][lrow] = bv.y;
        sm.gm.B[0][lc4 + 2][lrow] = bv.z; sm.gm.B[0][lc4 + 3][lrow] = bv.w;
    }
    __syncthreads();

    int buf = 0;
    const int NKT = DD / 8;   // 64
    for (int kt = 0; kt < NKT; kt++) {
        if (kt < NKT - 1) {
            av = *reinterpret_cast<const float4*>(Aptr + (kt + 1) * 8);
            bv = *reinterpret_cast<const float4*>(Bptr + (kt + 1) * 8);
        }
        #pragma unroll
        for (int k = 0; k < 8; k++) {
            // A pairs (duplicated values): rows ty*4..+3 and 64+ty*4..+3
            ulonglong2 a01 = *reinterpret_cast<const ulonglong2*>(&sm.gm.A[buf][k][ty * 8]);
            ulonglong2 a23 = *reinterpret_cast<const ulonglong2*>(&sm.gm.A[buf][k][ty * 8 + 4]);
            ulonglong2 a45 = *reinterpret_cast<const ulonglong2*>(&sm.gm.A[buf][k][128 + ty * 8]);
            ulonglong2 a67 = *reinterpret_cast<const ulonglong2*>(&sm.gm.A[buf][k][128 + ty * 8 + 4]);
            // B col-pairs (packed naturally)
            ulonglong2 b01 = *reinterpret_cast<const ulonglong2*>(&sm.gm.B[buf][k][tx * 4]);
            ulonglong2 b23 = *reinterpret_cast<const ulonglong2*>(&sm.gm.B[buf][k][tx * 4 + 64]);

            FFMA2(acc2[0][0], a01.x, b01.x); FFMA2(acc2[0][1], a01.x, b01.y);
            FFMA2(acc2[0][2], a01.x, b23.x); FFMA2(acc2[0][3], a01.x, b23.y);
            FFMA2(acc2[1][0], a01.y, b01.x); FFMA2(acc2[1][1], a01.y, b01.y);
            FFMA2(acc2[1][2], a01.y, b23.x); FFMA2(acc2[1][3], a01.y, b23.y);
            FFMA2(acc2[2][0], a23.x, b01.x); FFMA2(acc2[2][1], a23.x, b01.y);
            FFMA2(acc2[2][2], a23.x, b23.x); FFMA2(acc2[2][3], a23.x, b23.y);
            FFMA2(acc2[3][0], a23.y, b01.x); FFMA2(acc2[3][1], a23.y, b01.y);
            FFMA2(acc2[3][2], a23.y, b23.x); FFMA2(acc2[3][3], a23.y, b23.y);
            FFMA2(acc2[4][0], a45.x, b01.x); FFMA2(acc2[4][1], a45.x, b01.y);
            FFMA2(acc2[4][2], a45.x, b23.x); FFMA2(acc2[4][3], a45.x, b23.y);
            FFMA2(acc2[5][0], a45.y, b01.x); FFMA2(acc2[5][1], a45.y, b01.y);
            FFMA2(acc2[5][2], a45.y, b23.x); FFMA2(acc2[5][3], a45.y, b23.y);
            FFMA2(acc2[6][0], a67.x, b01.x); FFMA2(acc2[6][1], a67.x, b01.y);
            FFMA2(acc2[6][2], a67.x, b23.x); FFMA2(acc2[6][3], a67.x, b23.y);
            FFMA2(acc2[7][0], a67.y, b01.x); FFMA2(acc2[7][1], a67.y, b01.y);
            FFMA2(acc2[7][2], a67.y, b23.x); FFMA2(acc2[7][3], a67.y, b23.y);
        }
        if (kt < NKT - 1) {
            // Store prefetched tile into the OTHER buffer (not read this iter),
            // then a single barrier. Restores R8's overlap.
            const int nb = buf ^ 1;
            float2* Ad = reinterpret_cast<float2*>(&sm.gm.A[nb][0][0]);
            Ad[(lc4 + 0) * 128 + lrow] = make_float2(av.x, av.x);
            Ad[(lc4 + 1) * 128 + lrow] = make_float2(av.y, av.y);
            Ad[(lc4 + 2) * 128 + lrow] = make_float2(av.z, av.z);
            Ad[(lc4 + 3) * 128 + lrow] = make_float2(av.w, av.w);
            sm.gm.B[nb][lc4 + 0][lrow] = bv.x; sm.gm.B[nb][lc4 + 1][lrow] = bv.y;
            sm.gm.B[nb][lc4 + 2][lrow] = bv.z; sm.gm.B[nb][lc4 + 3][lrow] = bv.w;
            __syncthreads();
            buf = nb;
        }
    }

    // Unpack accumulators: accf[ii][jj]; col jj<4 -> tx*4+jj, else 64+tx*4+jj-4
    float accf[8][8];
    #pragma unroll
    for (int ii = 0; ii < 8; ii++)
        #pragma unroll
        for (int jp = 0; jp < 4; jp++)
            UNPK(accf[ii][2 * jp], accf[ii][2 * jp + 1], acc2[ii][jp]);

    // Diagonal elements live where ib==jb, tx==ty, ii==jj per half
    if (ib == jb && tx == ty) {
        #pragma unroll
        for (int q = 0; q < 4; q++) {
            g_diag[t * BB + jb + tx * 4 + q]      = accf[q][q];
            g_diag[t * BB + jb + 64 + tx * 4 + q] = accf[4 + q][4 + q];
        }
    }

    __syncthreads();   // done with gm smem, reuse as reduction space

    // Step 1: per-thread column max/argmax over its 8 rows
    #pragma unroll
    for (int jj = 0; jj < 8; jj++) {
        const int c = (jj < 4) ? tx * 4 + jj : 64 + tx * 4 + (jj - 4);
        float m = -3.402823466e38f; int arow = 0;
        #pragma unroll
        for (int ii = 0; ii < 8; ii++) {
            float v = accf[ii][jj];
            int grow = ib + ((ii < 4) ? ty * 4 + ii : 64 + ty * 4 + (ii - 4));
            if (v > m) { m = v; arow = grow; }
        }
        sm.red.m[ty][c] = m;
        sm.red.idx[ty][c] = arow;
    }
    __syncthreads();

    // Step 2: reduce 16 partials -> block-column max/argmax
    if (tid < 128) {
        float m = -3.402823466e38f; int am = 0;
        #pragma unroll
        for (int k = 0; k < 16; k++) {
            float v = sm.red.m[k][tid];
            if (v > m) { m = v; am = sm.red.idx[k][tid]; }
        }
        sm.red.m128[tid] = m;
        sm.red.am128[tid] = am;
    }
    __syncthreads();

    // Step 3: thresholded sum-exp vs block max (kills ~90% of expf)
    #pragma unroll
    for (int jj = 0; jj < 8; jj++) {
        const int c = (jj < 4) ? tx * 4 + jj : 64 + tx * 4 + (jj - 4);
        const float M = sm.red.m128[c];
        float s = 0.f;
        #pragma unroll
        for (int ii = 0; ii < 8; ii++) {
            float d = accf[ii][jj] - M;
            if (d > -30.0f) s += __expf(d);
        }
        sm.red.s[ty][c] = s;
    }
    __syncthreads();

    // Step 4: reduce s, write chunk partials
    if (tid < 128) {
        float s = 0.f;
        #pragma unroll
        for (int k = 0; k < 16; k++) s += sm.red.s[k][tid];
        const int pidx = ((t * 8 + ic) * BB) + jb + tid;
        g_pm[pidx]  = sm.red.m128[tid];
        g_ps[pidx]  = s;
        g_pam[pidx] = sm.red.am128[tid];
    }
}

// ---------------------------------------------------------------------------
// Combine 8 chunk-partials per column -> log_softmax diag + correctness flag
// ---------------------------------------------------------------------------
__global__ __launch_bounds__(256)
void cpc_combine_kernel()
{
    const int gid = blockIdx.x * blockDim.x + threadIdx.x;   // 0..12287
    const int t = gid >> 10;
    const int j = gid & (BB - 1);
    const int base = t * 8 * BB + j;

    float m = -3.402823466e38f; int am = 0;
    #pragma unroll
    for (int k = 0; k < 8; k++) {
        float mk = g_pm[base + k * BB];
        if (mk > m) { m = mk; am = g_pam[base + k * BB]; }
    }
    float s = 0.f;
    #pragma unroll
    for (int k = 0; k < 8; k++)
        s += g_ps[base + k * BB] * __expf(g_pm[base + k * BB] - m);

    const float lse = m + __logf(s);
    g_col[gid]           = g_diag[gid] - lse;
    g_col[gid + TT * BB] = (am == j) ? 1.0f : 0.0f;
}

// ---------------------------------------------------------------------------
// Deterministic single-block reduction -> (-loss, accuracy)
// ---------------------------------------------------------------------------
__global__ __launch_bounds__(1024)
void cpc_finalize_kernel(float* __restrict__ out)
{
    __shared__ float sv[1024];
    __shared__ float sc[1024];
    const int tid = threadIdx.x;
    const int N = TT * BB;

    float v = 0.f, c = 0.f;
    for (int k = tid; k < N; k += 1024) {
        v += g_col[k];
        c += g_col[k + N];
    }
    sv[tid] = v; sc[tid] = c;
    __syncthreads();
    #pragma unroll
    for (int st = 512; st > 0; st >>= 1) {
        if (tid < st) { sv[tid] += sv[tid + st]; sc[tid] += sc[tid + st]; }
        __syncthreads();
    }
    if (tid == 0) {
        out[0] = -(sv[0] / (float)N);
        out[1] = sc[0] / (float)N;
    }
}

// ---------------------------------------------------------------------------
extern "C" void kernel_launch(void* const* d_in, const int* in_sizes, int n_in,
                              void* d_out, int out_size)
{
    const float* predictions = (const float*)d_in[0];
    const float* x_future    = (const float*)d_in[1];
    float* out = (float*)d_out;

    dim3 ggrid(BB / 128, BB / 128, TT);   // (8, 8, 12)
    cpc_gemm_fused_kernel<<<ggrid, 256>>>(x_future, predictions);
    cpc_combine_kernel<<<(TT * BB) / 256, 256>>>();
    cpc_finalize_kernel<<<1, 1024>>>(out);
}